// round 15
// baseline (speedup 1.0000x reference)
#include <cuda_runtime.h>
#include <cuda_fp16.h>
#include <mma.h>
#include <stdint.h>

using namespace nvcuda;

// Problem dims
#define BATCH   256
#define TSEQ    1024
#define IN_D    128
#define HID     256
#define OUT_D   128

// Partitioning: 16 batch-groups x 8 unit-group CTAs; cluster of 8 = one batch group
#define NBG     16
#define NUG     8
#define MB      16            // batch rows per group
#define UPC     32            // hidden units per CTA
#define NROWS   128           // gate rows per CTA
#define KDIM    384           // [h(256) | x(128)]
#define KPAD    392           // padded K stride (halves)
#define ZPAD    132           // padded z stride (floats)
#define NTH     256
#define KH      16            // h-part k-steps
#define KSTEPS  24
#define NPKT    256           // 8B packets per producer slice (16 rows x 16 unit-pairs)

#define SW_ELEMS (NROWS*KPAD)          // 50176 halves
#define SA_ELEMS (MB*KPAD)             // 6272 halves per buffer

// smem byte offsets
#define OFF_SW   0
#define OFF_SA   (OFF_SW + SW_ELEMS*2)              // 100352
#define OFF_SZ   (OFF_SA + 2*SA_ELEMS*2)            // 125440
#define OFF_SB   (OFF_SZ + MB*ZPAD*4)               // 133888
#define OFF_SH   (OFF_SB + NROWS*4)                 // 134400
#define OFF_PKT  (OFF_SH + MB*UPC*2)                // 135424: u64[2][NUG][NPKT]
#define SMEM_BYTES (OFF_PKT + 2*NUG*NPKT*8)         // 168192

// Device-global state (g_h32 fully overwritten every launch -> deterministic)
__device__ float g_h32[BATCH*HID];

__device__ __forceinline__ float tanh_fast(float x) {
    float e = __expf(2.0f * x);
    return 1.0f - 2.0f / (e + 1.0f);
}
__device__ __forceinline__ float sigm_fast(float x) {
    return 1.0f / (1.0f + __expf(-x));
}
__device__ __forceinline__ unsigned long long lds_poll(uint32_t addr) {
    unsigned long long v;
    asm volatile("ld.volatile.shared.u64 %0, [%1];" : "=l"(v) : "r"(addr) : "memory");
    return v;
}
__device__ __forceinline__ void dsmem_send(uint32_t remote_addr, unsigned long long v) {
    asm volatile("st.shared::cluster.u64 [%0], %1;" :: "r"(remote_addr), "l"(v) : "memory");
}

__global__ void __launch_bounds__(NTH, 1) __cluster_dims__(NUG, 1, 1)
lstm_dsll_kernel(const float* __restrict__ x,
                 const float* __restrict__ Wgx, const float* __restrict__ bgx, const float* __restrict__ Wgh,
                 const float* __restrict__ Wix, const float* __restrict__ bix, const float* __restrict__ Wih,
                 const float* __restrict__ Wfx, const float* __restrict__ bfx, const float* __restrict__ Wfh,
                 const float* __restrict__ Wox, const float* __restrict__ boxp, const float* __restrict__ Woh,
                 const float* __restrict__ Wp, const float* __restrict__ bp,
                 float* __restrict__ out)
{
    extern __shared__ unsigned char smem_raw[];
    const uint32_t smb = (uint32_t)__cvta_generic_to_shared(smem_raw);
    __half* sW    = (__half*)(smem_raw + OFF_SW);
    __half* sA    = (__half*)(smem_raw + OFF_SA);     // [2][MB][KPAD]
    float*  sZ    = (float*)(smem_raw + OFF_SZ);
    float*  sBias = (float*)(smem_raw + OFF_SB);
    __half* sH    = (__half*)(smem_raw + OFF_SH);     // [MB][UPC]

    const int tid  = threadIdx.x;
    const int warp = tid >> 5;
    const int lid  = tid & 31;
    const int ug   = blockIdx.x % NUG;     // cluster rank
    const int bg   = blockIdx.x / NUG;

    // ---- Load weight slice into smem fp16: row n = gate*32+u, cols [Wh(256)|Wx(128)] ----
    {
        const float* WhA[4] = {Wgh, Wih, Wfh, Woh};
        const float* WxA[4] = {Wgx, Wix, Wfx, Wox};
        #pragma unroll
        for (int g = 0; g < 4; ++g) {
            const float* wh = WhA[g];
            const float* wx = WxA[g];
            for (int idx = tid; idx < UPC*KDIM; idx += NTH) {
                int ul = idx / KDIM;
                int k  = idx - ul*KDIM;
                int n  = g*UPC + ul;
                int ugl = ug*UPC + ul;
                float w = (k < HID) ? wh[ugl*HID + k] : wx[ugl*IN_D + (k - HID)];
                sW[n*KPAD + k] = __float2half_rn(w);
            }
        }
        if (tid < UPC) {
            const float* bxA[4] = {bgx, bix, bfx, boxp};
            #pragma unroll
            for (int g = 0; g < 4; ++g)
                sBias[g*UPC + tid] = bxA[g][ug*UPC + tid];
        }
    }

    // ---- Init: zero packet staging (tags=0), zero h region of buf0; x_0/x_1 -> bufs ----
    {
        // zero sPkt: 2*NUG*NPKT u64 = 32768 B = 2048 uint4
        uint4 z4; z4.x = z4.y = z4.z = z4.w = 0u;
        uint4* pk4 = (uint4*)(smem_raw + OFF_PKT);
        #pragma unroll
        for (int i = 0; i < 8; ++i)
            pk4[tid + i*NTH] = z4;

        for (int i = tid; i < MB*HID/2; i += NTH) {
            int row = i >> 7;
            int w2  = i & 127;
            *(uint32_t*)&sA[row*KPAD + w2*2] = 0u;
        }
        int row = tid >> 4;
        int q   = (tid & 15) * 8;
        #pragma unroll
        for (int bu = 0; bu < 2; ++bu) {
            const float* src = &x[(bg*MB + row)*(TSEQ*IN_D) + bu*IN_D + q];
            float4 v0 = *(const float4*)src;
            float4 v1 = *(const float4*)(src + 4);
            __half2 h0 = __floats2half2_rn(v0.x, v0.y), h1 = __floats2half2_rn(v0.z, v0.w);
            __half2 h2 = __floats2half2_rn(v1.x, v1.y), h3 = __floats2half2_rn(v1.z, v1.w);
            uint4 pk; pk.x = *(uint32_t*)&h0; pk.y = *(uint32_t*)&h1;
            pk.z = *(uint32_t*)&h2; pk.w = *(uint32_t*)&h3;
            *(uint4*)&sA[bu*SA_ELEMS + row*KPAD + HID + q] = pk;
        }
    }
    __syncthreads();

    // one-time cluster barrier: all staging zeroed before any peer pushes
    asm volatile("barrier.cluster.arrive.aligned;" ::: "memory");
    asm volatile("barrier.cluster.wait.aligned;"   ::: "memory");

    // precompute remote staging bases for all ranks
    uint32_t rbase[NUG];
    #pragma unroll
    for (int r = 0; r < NUG; ++r) {
        asm volatile("mapa.shared::cluster.u32 %0, %1, %2;"
                     : "=r"(rbase[r]) : "r"(smb + OFF_PKT), "r"(r));
    }

    // ---- B fragments in registers (loop-invariant weights) ----
    wmma::fragment<wmma::matrix_a, 16,16,16, __half, wmma::row_major> fa;
    wmma::fragment<wmma::matrix_b, 16,16,16, __half, wmma::col_major> fbr[KSTEPS];
    wmma::fragment<wmma::accumulator, 16,16,16, float> fc, fc2;
    const int n0 = warp * 16;
    #pragma unroll
    for (int kk = 0; kk < KSTEPS; ++kk)
        wmma::load_matrix_sync(fbr[kk], sW + n0*KPAD + kk*16, KPAD);

    // ---- Pre-loop X phase: fc = x_0 @ Wx^T (from buf0.x) ----
    wmma::fill_fragment(fc, 0.0f);
    #pragma unroll
    for (int kk = KH; kk < KSTEPS; ++kk) {
        wmma::load_matrix_sync(fa, sA + kk*16, KPAD);
        wmma::mma_sync(fc, fa, fbr[kk], fc);
    }

    // epilogue mapping: thread (b0=warp, uu=lid) handles rows b0 and b0+8, unit uu
    const int b0 = warp;
    const int uu = lid;
    float c0 = 0.0f, c1 = 0.0f;

    for (int t = 0; t < TSEQ; ++t) {
        const int p = t & 1;

        // ---- prefetch x_{t+2} into regs ----
        float4 xv0, xv1;
        {
            int tn  = (t + 2 < TSEQ) ? (t + 2) : (TSEQ - 1);
            int row = tid >> 4;
            int q   = (tid & 15) * 8;
            const float* src = &x[(bg*MB + row)*(TSEQ*IN_D) + tn*IN_D + q];
            xv0 = *(const float4*)src;
            xv1 = *(const float4*)(src + 4);
        }

        // ---- acquire h_t tile: warp w handles producer w (local LDS LL poll) ----
        if (t > 0) {
            if (warp == ug) {
                // own slice from local sH
                const int row = lid >> 1;
                const int seg = lid & 1;
                const uint4* src = (const uint4*)((const unsigned char*)sH + row*(UPC*2) + seg*32);
                uint4 v0s = src[0], v1s = src[1];
                __half* dst = &sA[p*SA_ELEMS + row*KPAD + warp*UPC + seg*16];
                ((uint4*)dst)[0] = v0s;
                ((uint4*)dst)[1] = v1s;
            } else {
                const uint32_t base = smb + OFF_PKT +
                    (uint32_t)(((p*NUG + warp)*NPKT + lid*8) * 8);
                const unsigned want = (unsigned)t;
                unsigned long long v[8];
                #pragma unroll
                for (int i = 0; i < 8; ++i) v[i] = 0ull;   // tag 0 != t (t>=1)
                int miss = 1;
                while (miss) {
                    #pragma unroll
                    for (int i = 0; i < 8; ++i)
                        if ((unsigned)(v[i] >> 32) != want) v[i] = lds_poll(base + i*8);
                    miss = 0;
                    #pragma unroll
                    for (int i = 0; i < 8; ++i)
                        miss |= ((unsigned)(v[i] >> 32) != want);
                }
                // scatter payloads: chunk c = r*16 + up  ->  sA[p][r][warp*32 + 2*up]
                #pragma unroll
                for (int i = 0; i < 8; ++i) {
                    int c  = lid*8 + i;
                    int r  = c >> 4;
                    int up = c & 15;
                    *(uint32_t*)&sA[p*SA_ELEMS + r*KPAD + warp*UPC + up*2] = (uint32_t)v[i];
                }
            }
        }
        __syncthreads();

        // ---- Phase H: accumulate h-part (k = 0..255), dual accumulator ----
        const __half* sAp = sA + p*SA_ELEMS;
        wmma::fill_fragment(fc2, 0.0f);
        #pragma unroll
        for (int kk = 0; kk < KH; kk += 2) {
            wmma::load_matrix_sync(fa, sAp + kk*16, KPAD);
            wmma::mma_sync(fc, fa, fbr[kk], fc);
            wmma::load_matrix_sync(fa, sAp + (kk+1)*16, KPAD);
            wmma::mma_sync(fc2, fa, fbr[kk+1], fc2);
        }
        #pragma unroll
        for (int e = 0; e < fc.num_elements; ++e) fc.x[e] += fc2.x[e];
        wmma::store_matrix_sync(sZ + n0, fc, ZPAD, wmma::mem_row_major);
        __syncthreads();

        // ---- Epilogue: gates, c/h update; publish LL packets via DSMEM ----
        float hv[2];
        #pragma unroll
        for (int j = 0; j < 2; ++j) {
            int b = b0 + j*8;
            const float* zr = &sZ[b*ZPAD];
            float zg = zr[uu]          + sBias[uu];
            float zi = zr[UPC   + uu]  + sBias[UPC   + uu];
            float zf = zr[2*UPC + uu]  + sBias[2*UPC + uu];
            float zo = zr[3*UPC + uu]  + sBias[3*UPC + uu];
            float gv = tanh_fast(zg);
            float iv = sigm_fast(zi);
            float fv = sigm_fast(zf);
            float ov = sigm_fast(zo);
            float& c = j ? c1 : c0;
            c = gv*iv + c*fv;
            hv[j] = tanh_fast(c) * ov;
            sH[b*UPC + uu] = __float2half_rn(hv[j]);
            if (t == TSEQ-1) g_h32[(bg*MB + b)*HID + ug*UPC + uu] = hv[j];
        }

        // pack + push to the 7 remote ranks' staging (tags ride with data; no fences)
        if (t < TSEQ-1) {
            unsigned my = ((unsigned)__half_as_ushort(__float2half_rn(hv[0])))
                        | (((unsigned)__half_as_ushort(__float2half_rn(hv[1]))) << 16);
            unsigned other = __shfl_xor_sync(0xffffffffu, my, 1);
            if (!(lid & 1)) {
                unsigned pa = (my & 0xFFFFu)  | ((other & 0xFFFFu) << 16);       // row b0
                unsigned pb = (my >> 16)      | (other & 0xFFFF0000u);           // row b0+8
                unsigned long long tag = ((unsigned long long)(unsigned)(t + 1)) << 32;
                unsigned long long pka = tag | (unsigned long long)pa;
                unsigned long long pkb = tag | (unsigned long long)pb;
                const int q  = p ^ 1;
                const int up = lid >> 1;
                uint32_t off_a = (uint32_t)(((q*NUG + ug)*NPKT + b0*16 + up) * 8);
                uint32_t off_b = (uint32_t)(((q*NUG + ug)*NPKT + (b0+8)*16 + up) * 8);
                #pragma unroll
                for (int r = 0; r < NUG; ++r) {
                    if (r != ug) {
                        dsmem_send(rbase[r] + off_a, pka);
                        dsmem_send(rbase[r] + off_b, pkb);
                    }
                }
            }
        }
        __syncthreads();

        // ---- Phase X for step t+1: fc = x_{t+1} @ Wx^T (buffer p^1) — overlaps flight ----
        wmma::fill_fragment(fc, 0.0f);
        const __half* sAx = sA + (p^1)*SA_ELEMS;
        #pragma unroll
        for (int kk = KH; kk < KSTEPS; ++kk) {
            wmma::load_matrix_sync(fa, sAx + kk*16, KPAD);
            wmma::mma_sync(fc, fa, fbr[kk], fc);
        }

        // ---- stage x_{t+2} into buffer p x-region ----
        {
            int row = tid >> 4;
            int qq  = (tid & 15) * 8;
            __half2 h0 = __floats2half2_rn(xv0.x, xv0.y), h1 = __floats2half2_rn(xv0.z, xv0.w);
            __half2 h2 = __floats2half2_rn(xv1.x, xv1.y), h3 = __floats2half2_rn(xv1.z, xv1.w);
            uint4 pk; pk.x = *(uint32_t*)&h0; pk.y = *(uint32_t*)&h1;
            pk.z = *(uint32_t*)&h2; pk.w = *(uint32_t*)&h3;
            *(uint4*)&sA[p*SA_ELEMS + row*KPAD + HID + qq] = pk;
        }
    }

    // ---- make g_h32 visible cluster-wide, then rank-0 CTAs project ----
    __threadfence();
    __syncthreads();
    asm volatile("barrier.cluster.arrive.aligned;" ::: "memory");
    asm volatile("barrier.cluster.wait.aligned;"   ::: "memory");

    if (ug == 0) {
        const int b     = tid >> 4;
        const int obase = (tid & 15) * 8;
        float acc[8];
        #pragma unroll
        for (int rr = 0; rr < 8; ++rr) acc[rr] = bp[obase + rr];
        const float* hrow = &g_h32[(bg*MB + b)*HID];
        for (int k = 0; k < HID; k += 4) {
            float4 hvv = __ldcg((const float4*)&hrow[k]);
            #pragma unroll
            for (int rr = 0; rr < 8; ++rr) {
                acc[rr] = fmaf(hvv.x, Wp[(obase + rr)*HID + k],     acc[rr]);
                acc[rr] = fmaf(hvv.y, Wp[(obase + rr)*HID + k + 1], acc[rr]);
                acc[rr] = fmaf(hvv.z, Wp[(obase + rr)*HID + k + 2], acc[rr]);
                acc[rr] = fmaf(hvv.w, Wp[(obase + rr)*HID + k + 3], acc[rr]);
            }
        }
        #pragma unroll
        for (int rr = 0; rr < 8; ++rr)
            out[(bg*MB + b)*OUT_D + obase + rr] = acc[rr];
    }
}

extern "C" void kernel_launch(void* const* d_in, const int* in_sizes, int n_in,
                              void* d_out, int out_size) {
    const float* x   = (const float*)d_in[0];
    const float* Wgx = (const float*)d_in[1];
    const float* bgx = (const float*)d_in[2];
    const float* Wgh = (const float*)d_in[3];
    const float* Wix = (const float*)d_in[4];
    const float* bix = (const float*)d_in[5];
    const float* Wih = (const float*)d_in[6];
    const float* Wfx = (const float*)d_in[7];
    const float* bfx = (const float*)d_in[8];
    const float* Wfh = (const float*)d_in[9];
    const float* Wox = (const float*)d_in[10];
    const float* box = (const float*)d_in[11];
    const float* Woh = (const float*)d_in[12];
    const float* Wp  = (const float*)d_in[13];
    const float* bp  = (const float*)d_in[14];
    float* out = (float*)d_out;

    static bool attr_set = false;
    if (!attr_set) {
        cudaFuncSetAttribute(lstm_dsll_kernel,
                             cudaFuncAttributeMaxDynamicSharedMemorySize, SMEM_BYTES);
        attr_set = true;
    }

    lstm_dsll_kernel<<<NBG*NUG, NTH, SMEM_BYTES>>>(
        x, Wgx, bgx, Wgh, Wix, bix, Wih, Wfx, bfx, Wfh, Wox, box, Woh, Wp, bp, out);
}

// round 16
// speedup vs baseline: 1.7473x; 1.7473x over previous
#include <cuda_runtime.h>
#include <cuda_fp16.h>
#include <mma.h>
#include <stdint.h>

using namespace nvcuda;

// Problem dims
#define BATCH   256
#define TSEQ    1024
#define IN_D    128
#define HID     256
#define OUT_D   128

// Partitioning: 16 batch-groups x 8 unit-group CTAs, LL global-L2 exchange
#define NBG     16
#define NUG     8
#define MB      16            // batch rows per group
#define UPC     32            // hidden units per CTA
#define NROWS   128           // gate rows per CTA (unit-major: n = unit*4 + gate)
#define KDIM    384           // [h(256) | x(128)]
#define KPAD    392           // padded K stride (halves)
#define NTH     256
#define KH      16            // h-part k-steps
#define KSTEPS  24
#define NPKT    256           // 8B packets per producer slice (16 rows x 16 unit-pairs)

#define SW_ELEMS (NROWS*KPAD)          // 50176 halves
#define SA_ELEMS (MB*KPAD)             // 6272 halves per buffer

// smem byte offsets
#define OFF_SW   0
#define OFF_SA   (SW_ELEMS*2)                       // 100352
#define OFF_SH   (OFF_SA + 2*SA_ELEMS*2)            // 125440
#define SMEM_BYTES (OFF_SH + MB*UPC*2)              // 126464

// Device-global state
__device__ unsigned long long g_hx[2][NBG][NUG][NPKT];  // LL packets: tag<<32 | 2xfp16
__device__ float    g_h32[BATCH*HID];                    // fp32 h_T for final projection
__device__ unsigned g_done[NBG];                         // completion counters

__device__ __forceinline__ float tanh_fast(float x) {
    float e = __expf(2.0f * x);
    return 1.0f - 2.0f / (e + 1.0f);
}
__device__ __forceinline__ float sigm_fast(float x) {
    return 1.0f / (1.0f + __expf(-x));
}
__device__ __forceinline__ unsigned long long ll_poll(const unsigned long long* p) {
    unsigned long long v;
    asm volatile("ld.global.cg.b64 %0, [%1];" : "=l"(v) : "l"(p) : "memory");
    return v;
}
__device__ __forceinline__ void ll_send(unsigned long long* p, unsigned long long v) {
    asm volatile("st.global.cg.b64 [%0], %1;" :: "l"(p), "l"(v) : "memory");
}
__device__ __forceinline__ unsigned ld_acquire_gpu(const unsigned* p) {
    unsigned v;
    asm volatile("ld.acquire.gpu.global.u32 %0, [%1];" : "=r"(v) : "l"(p) : "memory");
    return v;
}

__global__ void lstm_init_kernel() {
    int i = blockIdx.x * blockDim.x + threadIdx.x;
    int n = 2*NBG*NUG*NPKT;                 // 8192 u64
    if (i < n) ((unsigned long long*)g_hx)[i] = 0ull;
    if (i < NBG) g_done[i] = 0u;
}

__global__ void __launch_bounds__(NTH, 1)
lstm_ll2_kernel(const float* __restrict__ x,
                const float* __restrict__ Wgx, const float* __restrict__ bgx, const float* __restrict__ Wgh,
                const float* __restrict__ Wix, const float* __restrict__ bix, const float* __restrict__ Wih,
                const float* __restrict__ Wfx, const float* __restrict__ bfx, const float* __restrict__ Wfh,
                const float* __restrict__ Wox, const float* __restrict__ boxp, const float* __restrict__ Woh,
                const float* __restrict__ Wp, const float* __restrict__ bp,
                float* __restrict__ out)
{
    extern __shared__ unsigned char smem_raw[];
    __half* sW = (__half*)(smem_raw + OFF_SW);
    __half* sA = (__half*)(smem_raw + OFF_SA);     // [2][MB][KPAD]
    __half* sH = (__half*)(smem_raw + OFF_SH);     // [MB][UPC]

    const int tid  = threadIdx.x;
    const int warp = tid >> 5;
    const int lid  = tid & 31;
    const int ug   = blockIdx.x % NUG;
    const int bg   = blockIdx.x / NUG;

    // ---- Load weight slice, UNIT-MAJOR rows: n = unit_local*4 + gate ----
    {
        const float* WhA[4] = {Wgh, Wih, Wfh, Woh};
        const float* WxA[4] = {Wgx, Wix, Wfx, Wox};
        for (int idx = tid; idx < NROWS*KDIM; idx += NTH) {
            int n = idx / KDIM;
            int k = idx - n*KDIM;
            int u = n >> 2, g = n & 3;
            int gu = ug*UPC + u;
            float w = (k < HID) ? WhA[g][gu*HID + k] : WxA[g][gu*IN_D + (k - HID)];
            sW[n*KPAD + k] = __float2half_rn(w);
        }
    }

    // ---- Init: zero h region of buf0; x_0 -> buf0.x, x_1 -> buf1.x ----
    {
        for (int i = tid; i < MB*HID/2; i += NTH) {
            int row = i >> 7;
            int w2  = i & 127;
            *(uint32_t*)&sA[row*KPAD + w2*2] = 0u;
        }
        int row = tid >> 4;
        int q8  = (tid & 15) * 8;
        #pragma unroll
        for (int bu = 0; bu < 2; ++bu) {
            const float* src = &x[(bg*MB + row)*(TSEQ*IN_D) + bu*IN_D + q8];
            float4 v0 = *(const float4*)src;
            float4 v1 = *(const float4*)(src + 4);
            __half2 h0 = __floats2half2_rn(v0.x, v0.y), h1 = __floats2half2_rn(v0.z, v0.w);
            __half2 h2 = __floats2half2_rn(v1.x, v1.y), h3 = __floats2half2_rn(v1.z, v1.w);
            uint4 pk; pk.x = *(uint32_t*)&h0; pk.y = *(uint32_t*)&h1;
            pk.z = *(uint32_t*)&h2; pk.w = *(uint32_t*)&h3;
            *(uint4*)&sA[bu*SA_ELEMS + row*KPAD + HID + q8] = pk;
        }
    }
    __syncthreads();

    // ---- B fragments in registers (loop-invariant weights) ----
    wmma::fragment<wmma::matrix_a, 16,16,16, __half, wmma::row_major> fa;
    wmma::fragment<wmma::matrix_b, 16,16,16, __half, wmma::col_major> fbr[KSTEPS];
    wmma::fragment<wmma::accumulator, 16,16,16, float> fc, fc2;
    const int n0 = warp * 16;
    #pragma unroll
    for (int kk = 0; kk < KSTEPS; ++kk)
        wmma::load_matrix_sync(fbr[kk], sW + n0*KPAD + kk*16, KPAD);

    // ---- Pre-loop X phase: fc = x_0 @ Wx^T (from buf0.x) ----
    wmma::fill_fragment(fc, 0.0f);
    #pragma unroll
    for (int kk = KH; kk < KSTEPS; ++kk) {
        wmma::load_matrix_sync(fa, sA + kk*16, KPAD);
        wmma::mma_sync(fc, fa, fbr[kk], fc);
    }

    // ---- per-lane epilogue mapping (fragment-direct) ----
    const int q  = lid & 3;          // quad column pair
    const int r  = lid >> 2;         // rows r and r+8
    const int ul = ((q & 1) << 1) + (q >> 1);   // unit_local within warp's 4 units
    const int gu_lane = ug*UPC + warp*4 + ul;
    const float bias_g = bgx[gu_lane], bias_i = bix[gu_lane];
    const float bias_f = bfx[gu_lane], bias_o = boxp[gu_lane];
    float c_a = 0.0f, c_b = 0.0f;    // cell state rows r, r+8

    for (int t = 0; t < TSEQ; ++t) {
        const int p = t & 1;

        // ---- prefetch x_{t+2} into regs ----
        float4 xv0, xv1;
        {
            int tn  = (t + 2 < TSEQ) ? (t + 2) : (TSEQ - 1);
            int row = tid >> 4;
            int q8  = (tid & 15) * 8;
            const float* src = &x[(bg*MB + row)*(TSEQ*IN_D) + tn*IN_D + q8];
            xv0 = *(const float4*)src;
            xv1 = *(const float4*)(src + 4);
        }

        const __half* sAp = sA + p*SA_ELEMS;
        wmma::fill_fragment(fc2, 0.0f);

        if (t > 0) {
            // ---- acquire h_t tile: warp w handles producer w (LL packets) ----
            if (warp == ug) {
                const int row = lid >> 1;
                const int seg = lid & 1;
                const uint4* src = (const uint4*)((const unsigned char*)sH + row*(UPC*2) + seg*32);
                uint4 v0s = src[0], v1s = src[1];
                __half* dst = &sA[p*SA_ELEMS + row*KPAD + warp*UPC + seg*16];
                ((uint4*)dst)[0] = v0s;
                ((uint4*)dst)[1] = v1s;
            } else {
                const unsigned long long* src = &g_hx[p][bg][warp][lid*8];
                const unsigned want = (unsigned)t;
                unsigned long long v[8];
                #pragma unroll
                for (int i = 0; i < 8; ++i) v[i] = 0ull;
                int miss = 1;
                while (miss) {
                    #pragma unroll
                    for (int i = 0; i < 8; ++i)
                        if ((unsigned)(v[i] >> 32) != want) v[i] = ll_poll(src + i);
                    miss = 0;
                    #pragma unroll
                    for (int i = 0; i < 8; ++i)
                        miss |= ((unsigned)(v[i] >> 32) != want);
                }
                #pragma unroll
                for (int i = 0; i < 8; ++i) {
                    int c  = lid*8 + i;
                    int rr = c >> 4;
                    int up = c & 15;
                    *(uint32_t*)&sA[p*SA_ELEMS + rr*KPAD + warp*UPC + up*2] = (uint32_t)v[i];
                }
            }

            // ---- split-phase H GEMM: group A (w0-3, producers 0-3, k0..7),
            //      group B (w4-7, producers 4-7, k8..15); swap halves after mid-sync ----
            if (warp < 4) {
                asm volatile("bar.sync 1, 128;" ::: "memory");
                #pragma unroll
                for (int kk = 0; kk < 8; kk += 2) {
                    wmma::load_matrix_sync(fa, sAp + kk*16, KPAD);
                    wmma::mma_sync(fc, fa, fbr[kk], fc);
                    wmma::load_matrix_sync(fa, sAp + (kk+1)*16, KPAD);
                    wmma::mma_sync(fc2, fa, fbr[kk+1], fc2);
                }
                __syncthreads();
                #pragma unroll
                for (int kk = 8; kk < 16; kk += 2) {
                    wmma::load_matrix_sync(fa, sAp + kk*16, KPAD);
                    wmma::mma_sync(fc, fa, fbr[kk], fc);
                    wmma::load_matrix_sync(fa, sAp + (kk+1)*16, KPAD);
                    wmma::mma_sync(fc2, fa, fbr[kk+1], fc2);
                }
            } else {
                asm volatile("bar.sync 2, 128;" ::: "memory");
                #pragma unroll
                for (int kk = 8; kk < 16; kk += 2) {
                    wmma::load_matrix_sync(fa, sAp + kk*16, KPAD);
                    wmma::mma_sync(fc, fa, fbr[kk], fc);
                    wmma::load_matrix_sync(fa, sAp + (kk+1)*16, KPAD);
                    wmma::mma_sync(fc2, fa, fbr[kk+1], fc2);
                }
                __syncthreads();
                #pragma unroll
                for (int kk = 0; kk < 8; kk += 2) {
                    wmma::load_matrix_sync(fa, sAp + kk*16, KPAD);
                    wmma::mma_sync(fc, fa, fbr[kk], fc);
                    wmma::load_matrix_sync(fa, sAp + (kk+1)*16, KPAD);
                    wmma::mma_sync(fc2, fa, fbr[kk+1], fc2);
                }
            }
        } else {
            // t == 0: buffer0 h-region is zeroed; plain dual-acc GEMM
            #pragma unroll
            for (int kk = 0; kk < KH; kk += 2) {
                wmma::load_matrix_sync(fa, sAp + kk*16, KPAD);
                wmma::mma_sync(fc, fa, fbr[kk], fc);
                wmma::load_matrix_sync(fa, sAp + (kk+1)*16, KPAD);
                wmma::mma_sync(fc2, fa, fbr[kk+1], fc2);
            }
        }
        #pragma unroll
        for (int e = 0; e < 8; ++e) fc.x[e] += fc2.x[e];

        // ---- fragment-direct epilogue: reassemble 4 gates per lane via shfl(1) ----
        float recv[4];
        const bool odd = (q & 1);
        #pragma unroll
        for (int i = 0; i < 4; ++i) {
            float s = odd ? fc.x[i] : fc.x[4 + i];
            recv[i] = __shfl_xor_sync(0xffffffffu, s, 1);
        }
        float zg0, zi0, zf0, zo0, zg1, zi1, zf1, zo1;
        if (!odd) {
            zg0 = fc.x[0]; zi0 = fc.x[1]; zf0 = recv[0]; zo0 = recv[1];
            zg1 = fc.x[2]; zi1 = fc.x[3]; zf1 = recv[2]; zo1 = recv[3];
        } else {
            zg0 = recv[0]; zi0 = recv[1]; zf0 = fc.x[4]; zo0 = fc.x[5];
            zg1 = recv[2]; zi1 = recv[3]; zf1 = fc.x[6]; zo1 = fc.x[7];
        }
        float gv0 = tanh_fast(zg0 + bias_g);
        float iv0 = sigm_fast(zi0 + bias_i);
        float fv0 = sigm_fast(zf0 + bias_f);
        float ov0 = sigm_fast(zo0 + bias_o);
        c_a = gv0*iv0 + c_a*fv0;
        float h0 = tanh_fast(c_a) * ov0;

        float gv1 = tanh_fast(zg1 + bias_g);
        float iv1 = sigm_fast(zi1 + bias_i);
        float fv1 = sigm_fast(zf1 + bias_f);
        float ov1 = sigm_fast(zo1 + bias_o);
        c_b = gv1*iv1 + c_b*fv1;
        float h1 = tanh_fast(c_b) * ov1;

        // ---- pack unit pairs via shfl(2); lanes q<2 publish + stage ----
        unsigned comb = (unsigned)__half_as_ushort(__float2half_rn(h0))
                      | ((unsigned)__half_as_ushort(__float2half_rn(h1)) << 16);
        unsigned pcomb = __shfl_xor_sync(0xffffffffu, comb, 2);
        if (!(lid & 2)) {
            unsigned pa = (comb & 0xFFFFu) | ((pcomb & 0xFFFFu) << 16);   // row r
            unsigned pb = (comb >> 16)     | (pcomb & 0xFFFF0000u);       // row r+8
            const int up = warp*2 + q;                                    // q in {0,1}
            if (t < TSEQ-1) {
                unsigned long long tag = ((unsigned long long)(unsigned)(t + 1)) << 32;
                unsigned long long* dst = &g_hx[p ^ 1][bg][ug][0];
                ll_send(dst + (r*16 + up),      tag | (unsigned long long)pa);
                ll_send(dst + ((r+8)*16 + up),  tag | (unsigned long long)pb);
                *(uint32_t*)&sH[r*UPC + up*2]       = pa;
                *(uint32_t*)&sH[(r+8)*UPC + up*2]   = pb;
            }
        }
        if (t == TSEQ-1) {
            g_h32[(bg*MB + r)*HID + gu_lane]     = h0;
            g_h32[(bg*MB + r + 8)*HID + gu_lane] = h1;
        }
        __syncthreads();

        // ---- Phase X for step t+1: fc = x_{t+1} @ Wx^T (buffer p^1) — overlaps comm ----
        wmma::fill_fragment(fc, 0.0f);
        const __half* sAx = sA + (p^1)*SA_ELEMS;
        #pragma unroll
        for (int kk = KH; kk < KSTEPS; ++kk) {
            wmma::load_matrix_sync(fa, sAx + kk*16, KPAD);
            wmma::mma_sync(fc, fa, fbr[kk], fc);
        }

        // ---- stage x_{t+2} into buffer p x-region ----
        {
            int row = tid >> 4;
            int q8  = (tid & 15) * 8;
            __half2 hh0 = __floats2half2_rn(xv0.x, xv0.y), hh1 = __floats2half2_rn(xv0.z, xv0.w);
            __half2 hh2 = __floats2half2_rn(xv1.x, xv1.y), hh3 = __floats2half2_rn(xv1.z, xv1.w);
            uint4 pk; pk.x = *(uint32_t*)&hh0; pk.y = *(uint32_t*)&hh1;
            pk.z = *(uint32_t*)&hh2; pk.w = *(uint32_t*)&hh3;
            *(uint4*)&sA[p*SA_ELEMS + row*KPAD + HID + q8] = pk;
        }
    }

    // ---- completion: publish g_h32 visibility, then ug==0 CTAs project ----
    __threadfence();
    __syncthreads();
    if (tid == 0) atomicAdd(&g_done[bg], 1u);

    if (ug == 0) {
        if (tid == 0) {
            while (ld_acquire_gpu(&g_done[bg]) < NUG) { }
        }
        __syncthreads();

        const int b     = tid >> 4;
        const int obase = (tid & 15) * 8;
        float acc[8];
        #pragma unroll
        for (int rr = 0; rr < 8; ++rr) acc[rr] = bp[obase + rr];
        const float* hrow = &g_h32[(bg*MB + b)*HID];
        for (int k = 0; k < HID; k += 4) {
            float4 hvv = __ldcg((const float4*)&hrow[k]);
            #pragma unroll
            for (int rr = 0; rr < 8; ++rr) {
                acc[rr] = fmaf(hvv.x, Wp[(obase + rr)*HID + k],     acc[rr]);
                acc[rr] = fmaf(hvv.y, Wp[(obase + rr)*HID + k + 1], acc[rr]);
                acc[rr] = fmaf(hvv.z, Wp[(obase + rr)*HID + k + 2], acc[rr]);
                acc[rr] = fmaf(hvv.w, Wp[(obase + rr)*HID + k + 3], acc[rr]);
            }
        }
        #pragma unroll
        for (int rr = 0; rr < 8; ++rr)
            out[(bg*MB + b)*OUT_D + obase + rr] = acc[rr];
    }
}

extern "C" void kernel_launch(void* const* d_in, const int* in_sizes, int n_in,
                              void* d_out, int out_size) {
    const float* x   = (const float*)d_in[0];
    const float* Wgx = (const float*)d_in[1];
    const float* bgx = (const float*)d_in[2];
    const float* Wgh = (const float*)d_in[3];
    const float* Wix = (const float*)d_in[4];
    const float* bix = (const float*)d_in[5];
    const float* Wih = (const float*)d_in[6];
    const float* Wfx = (const float*)d_in[7];
    const float* bfx = (const float*)d_in[8];
    const float* Wfh = (const float*)d_in[9];
    const float* Wox = (const float*)d_in[10];
    const float* box = (const float*)d_in[11];
    const float* Woh = (const float*)d_in[12];
    const float* Wp  = (const float*)d_in[13];
    const float* bp  = (const float*)d_in[14];
    float* out = (float*)d_out;

    static bool attr_set = false;
    if (!attr_set) {
        cudaFuncSetAttribute(lstm_ll2_kernel,
                             cudaFuncAttributeMaxDynamicSharedMemorySize, SMEM_BYTES);
        attr_set = true;
    }

    lstm_init_kernel<<<32, 256>>>();
    lstm_ll2_kernel<<<NBG*NUG, NTH, SMEM_BYTES>>>(
        x, Wgx, bgx, Wgh, Wix, bix, Wih, Wfx, bfx, Wfh, Wox, box, Woh, Wp, bp, out);
}